// round 1
// baseline (speedup 1.0000x reference)
#include <cuda_runtime.h>

// Problem constants (fixed by the reference setup_inputs)
#define TSEQ   2048
#define DMODEL 2048
#define NHEADS 16
#define DHEAD  128
#define BATCH  2
#define BROWS  (BATCH * TSEQ)      // 4096
#define QKVW   (3 * DMODEL)        // 6144
#define NBH    (BATCH * NHEADS)    // 32

// Scratch (device globals: allocation-free per harness rules)
__device__ float g_xn [(long long)BROWS * DMODEL];            // 32 MB
__device__ float g_qkv[(long long)BROWS * QKVW];              // 96 MB
__device__ float g_S  [(long long)NBH * TSEQ * TSEQ];         // 512 MB (scores -> probs in-place)
__device__ float g_y  [(long long)BROWS * DMODEL];            // 32 MB

// ---------------------------------------------------------------------------
// Reductions
// ---------------------------------------------------------------------------
__device__ __forceinline__ float warpMax(float v) {
#pragma unroll
    for (int o = 16; o; o >>= 1) v = fmaxf(v, __shfl_xor_sync(0xffffffffu, v, o));
    return v;
}
__device__ __forceinline__ float warpSum(float v) {
#pragma unroll
    for (int o = 16; o; o >>= 1) v += __shfl_xor_sync(0xffffffffu, v, o);
    return v;
}

// ---------------------------------------------------------------------------
// RMSNorm: one block per row (4096 rows of 2048)
// ---------------------------------------------------------------------------
__global__ __launch_bounds__(256) void rmsnorm_kernel(
    const float* __restrict__ x, const float* __restrict__ w, float* __restrict__ xn)
{
    long long base = (long long)blockIdx.x * DMODEL;
    int tid = threadIdx.x;
    const float4* xr = (const float4*)(x + base);
    float4 v0 = xr[tid];
    float4 v1 = xr[tid + 256];
    float s = v0.x*v0.x + v0.y*v0.y + v0.z*v0.z + v0.w*v0.w
            + v1.x*v1.x + v1.y*v1.y + v1.z*v1.z + v1.w*v1.w;

    __shared__ float sh[8];
    s = warpSum(s);
    if ((tid & 31) == 0) sh[tid >> 5] = s;
    __syncthreads();
    float tot = 0.f;
#pragma unroll
    for (int i = 0; i < 8; i++) tot += sh[i];

    float r = rsqrtf(tot / (float)DMODEL + 1e-6f);

    const float4* wr = (const float4*)w;
    float4 w0 = wr[tid], w1 = wr[tid + 256];
    float4 o0, o1;
    o0.x = v0.x*r*w0.x; o0.y = v0.y*r*w0.y; o0.z = v0.z*r*w0.z; o0.w = v0.w*r*w0.w;
    o1.x = v1.x*r*w1.x; o1.y = v1.y*r*w1.y; o1.z = v1.z*r*w1.z; o1.w = v1.w*r*w1.w;
    float4* outr = (float4*)(xn + base);
    outr[tid] = o0;
    outr[tid + 256] = o1;
}

// ---------------------------------------------------------------------------
// Tiled SGEMM: 128x128 C-tile, BK=8, 256 threads, 8x8 per thread.
// A is always K-major (row stride lda).
// BN_MAJOR = false : B is K-major [N,K]  -> C = A * B^T   ("TN", torch Linear)
// BN_MAJOR = true  : B is N-major [K,N]  -> C = A * B     ("NN", P*V)
// CAUSAL (TN):  skip C tiles strictly above the diagonal (bn > bm).
// CAUSAL (NN):  cap K at (bm+1)*BM  (trapezoid read of P).
// Batched over blockIdx.z = b*16 + h with separate b/h strides.
// ---------------------------------------------------------------------------
template<bool BN_MAJOR, bool CAUSAL>
__global__ __launch_bounds__(256) void gemm_kernel(
    const float* __restrict__ A, int lda, long long Ab, long long Ah,
    const float* __restrict__ B, int ldb, long long Bb, long long Bh,
    float*       __restrict__ C, int ldc, long long Cb, long long Ch,
    int M, int N, int K, float scale)
{
    const int BM = 128, BN = 128, BK = 8;
    int bm = blockIdx.y, bn = blockIdx.x;
    if (CAUSAL && !BN_MAJOR && bn > bm) return;

    long long zb = blockIdx.z >> 4, zh = blockIdx.z & 15;
    A += zb * Ab + zh * Ah + (long long)bm * BM * lda;
    B += zb * Bb + zh * Bh;
    if (!BN_MAJOR) B += (long long)bn * BN * ldb;
    else           B += bn * BN;
    C += zb * Cb + zh * Ch + (long long)bm * BM * ldc + bn * BN;

    int Kend = K;
    if (CAUSAL && BN_MAJOR) {
        int cap = (bm + 1) * BM;
        Kend = (cap < K) ? cap : K;
    }

    __shared__ float As[BK][BM];
    __shared__ float Bs[BK][BN];

    int tid  = threadIdx.x;
    int lrow = tid >> 1;          // 0..127
    int lcol = (tid & 1) * 4;     // 0 or 4
    int brow = tid >> 5;          // 0..7   (NN B load)
    int bcol = (tid & 31) * 4;    // 0..124 (NN B load)
    int tr = (tid >> 4) << 3;     // 0..120
    int tc = (tid & 15) << 3;     // 0..120

    float acc[8][8] = {};

    for (int k0 = 0; k0 < Kend; k0 += BK) {
        float4 a4 = *(const float4*)(A + (long long)lrow * lda + k0 + lcol);
        As[lcol + 0][lrow] = a4.x;
        As[lcol + 1][lrow] = a4.y;
        As[lcol + 2][lrow] = a4.z;
        As[lcol + 3][lrow] = a4.w;

        if (!BN_MAJOR) {
            float4 b4 = *(const float4*)(B + (long long)lrow * ldb + k0 + lcol);
            Bs[lcol + 0][lrow] = b4.x;
            Bs[lcol + 1][lrow] = b4.y;
            Bs[lcol + 2][lrow] = b4.z;
            Bs[lcol + 3][lrow] = b4.w;
        } else {
            float4 b4 = *(const float4*)(B + (long long)(k0 + brow) * ldb + bcol);
            *(float4*)&Bs[brow][bcol] = b4;
        }
        __syncthreads();

#pragma unroll
        for (int k = 0; k < BK; k++) {
            float4 a0 = *(const float4*)&As[k][tr];
            float4 a1 = *(const float4*)&As[k][tr + 4];
            float4 b0 = *(const float4*)&Bs[k][tc];
            float4 b1 = *(const float4*)&Bs[k][tc + 4];
            float ar[8] = {a0.x, a0.y, a0.z, a0.w, a1.x, a1.y, a1.z, a1.w};
            float br[8] = {b0.x, b0.y, b0.z, b0.w, b1.x, b1.y, b1.z, b1.w};
#pragma unroll
            for (int i = 0; i < 8; i++)
#pragma unroll
                for (int j = 0; j < 8; j++)
                    acc[i][j] += ar[i] * br[j];
        }
        __syncthreads();
    }

#pragma unroll
    for (int i = 0; i < 8; i++) {
#pragma unroll
        for (int j = 0; j < 8; j += 4) {
            float4 o;
            o.x = acc[i][j + 0] * scale;
            o.y = acc[i][j + 1] * scale;
            o.z = acc[i][j + 2] * scale;
            o.w = acc[i][j + 3] * scale;
            *(float4*)(C + (long long)(tr + i) * ldc + tc + j) = o;
        }
    }
}

// ---------------------------------------------------------------------------
// Causal softmax, in place on the score buffer.
// Row i: entries j<=i are valid; j>i written as exact 0 (matches reference:
// exp(s - 10000 - max) underflows to 0 in fp32).
// grid = (TSEQ, NBH), 256 threads, 8 elements per thread (2048 exactly).
// ---------------------------------------------------------------------------
__global__ __launch_bounds__(256) void softmax_causal(float* __restrict__ S)
{
    int i = blockIdx.x;
    long long base = (long long)blockIdx.y * TSEQ * TSEQ + (long long)i * TSEQ;
    float* row = S + base;
    int valid = i + 1;
    int tid = threadIdx.x;

    float e[8];
    float m = -1e30f;
#pragma unroll
    for (int l = 0; l < 8; l++) {
        int j = tid + l * 256;
        float s = (j < valid) ? row[j] : -1e30f;
        e[l] = s;
        m = fmaxf(m, s);
    }

    __shared__ float sh[8];
    m = warpMax(m);
    if ((tid & 31) == 0) sh[tid >> 5] = m;
    __syncthreads();
    float bm = sh[0];
#pragma unroll
    for (int w = 1; w < 8; w++) bm = fmaxf(bm, sh[w]);
    __syncthreads();

    float sum = 0.f;
#pragma unroll
    for (int l = 0; l < 8; l++) {
        int j = tid + l * 256;
        if (j < valid) { e[l] = expf(e[l] - bm); sum += e[l]; }
        else           { e[l] = 0.f; }
    }
    sum = warpSum(sum);
    if ((tid & 31) == 0) sh[tid >> 5] = sum;
    __syncthreads();
    float bs = 0.f;
#pragma unroll
    for (int w = 0; w < 8; w++) bs += sh[w];
    float inv = 1.0f / bs;

#pragma unroll
    for (int l = 0; l < 8; l++) {
        int j = tid + l * 256;
        row[j] = e[l] * inv;
    }
}

// ---------------------------------------------------------------------------
// Launch
// ---------------------------------------------------------------------------
extern "C" void kernel_launch(void* const* d_in, const int* in_sizes, int n_in,
                              void* d_out, int out_size)
{
    const float* x    = (const float*)d_in[0];
    const float* nw   = (const float*)d_in[1];
    const float* wqkv = (const float*)d_in[2];
    const float* wout = (const float*)d_in[3];
    float* out = (float*)d_out;

    float *xn, *qkv, *S, *y;
    cudaGetSymbolAddress((void**)&xn,  g_xn);
    cudaGetSymbolAddress((void**)&qkv, g_qkv);
    cudaGetSymbolAddress((void**)&S,   g_S);
    cudaGetSymbolAddress((void**)&y,   g_y);

    const long long QKV_B = (long long)TSEQ * QKVW;        // per-batch stride in qkv
    const long long S_B   = 16LL * TSEQ * TSEQ;            // per-batch stride in S
    const long long S_H   = (long long)TSEQ * TSEQ;        // per-head stride in S

    // 1) RMSNorm
    rmsnorm_kernel<<<BROWS, 256>>>(x, nw, xn);

    // 2) qkv = xn @ w_qkv^T   [4096,2048] x [6144,2048]^T -> [4096,6144]
    gemm_kernel<false, false><<<dim3(QKVW / 128, BROWS / 128, 1), 256>>>(
        xn,   DMODEL, 0, 0,
        wqkv, DMODEL, 0, 0,
        qkv,  QKVW,   0, 0,
        BROWS, QKVW, DMODEL, 1.0f);

    // 3) S = Q @ K^T / sqrt(Dh)  (batched over b,h; skip tiles above diagonal)
    gemm_kernel<false, true><<<dim3(TSEQ / 128, TSEQ / 128, NBH), 256>>>(
        qkv,          QKVW, QKV_B, DHEAD,        // Q: col offset h*128
        qkv + DMODEL, QKVW, QKV_B, DHEAD,        // K: section offset 2048
        S,            TSEQ, S_B,   S_H,
        TSEQ, TSEQ, DHEAD, 0.08838834764831845f);

    // 4) causal softmax, in place
    softmax_causal<<<dim3(TSEQ, NBH), 256>>>(S);

    // 5) y = P @ V  (trapezoid K-cap), written into merged-head layout
    gemm_kernel<true, true><<<dim3(1, TSEQ / 128, NBH), 256>>>(
        S,              TSEQ, S_B, S_H,
        qkv + 2*DMODEL, QKVW, QKV_B, DHEAD,      // V section
        y,              DMODEL, (long long)TSEQ * DMODEL, DHEAD,
        TSEQ, DHEAD, TSEQ, 1.0f);

    // 6) out = y @ w_out^T
    gemm_kernel<false, false><<<dim3(DMODEL / 128, BROWS / 128, 1), 256>>>(
        y,    DMODEL, 0, 0,
        wout, DMODEL, 0, 0,
        out,  DMODEL, 0, 0,
        BROWS, DMODEL, DMODEL, 1.0f);
}

// round 3
// speedup vs baseline: 2.7502x; 2.7502x over previous
#include <cuda_runtime.h>
#include <cuda_bf16.h>
#include <cstdint>

// Problem constants
#define TSEQ   2048
#define DMODEL 2048
#define NHEADS 16
#define DHEAD  128
#define BATCH  2
#define BROWS  (BATCH * TSEQ)      // 4096
#define QKVW   (3 * DMODEL)        // 6144
#define NBH    (BATCH * NHEADS)    // 32

typedef __nv_bfloat16 bf16;

// ---------------------------------------------------------------------------
// Scratch (device globals: allocation-free per harness rules)
// ---------------------------------------------------------------------------
__device__ bf16  g_xn_hi [(long long)BROWS * DMODEL];
__device__ bf16  g_xn_lo [(long long)BROWS * DMODEL];
__device__ bf16  g_wqkv_hi[(long long)QKVW * DMODEL];
__device__ bf16  g_wqkv_lo[(long long)QKVW * DMODEL];
__device__ bf16  g_wout_hi[(long long)DMODEL * DMODEL];
__device__ bf16  g_wout_lo[(long long)DMODEL * DMODEL];
__device__ bf16  g_qkv_hi[(long long)BROWS * QKVW];
__device__ bf16  g_qkv_lo[(long long)BROWS * QKVW];
__device__ bf16  g_vt_hi [(long long)NBH * DHEAD * TSEQ];
__device__ bf16  g_vt_lo [(long long)NBH * DHEAD * TSEQ];
__device__ float g_S     [(long long)NBH * TSEQ * TSEQ];   // scores fp32
__device__ bf16  g_P_hi  [(long long)NBH * TSEQ * TSEQ];
__device__ bf16  g_P_lo  [(long long)NBH * TSEQ * TSEQ];
__device__ bf16  g_y_hi  [(long long)BROWS * DMODEL];
__device__ bf16  g_y_lo  [(long long)BROWS * DMODEL];

// ---------------------------------------------------------------------------
// fp32 -> (bf16 hi, bf16 lo) split helpers
// ---------------------------------------------------------------------------
__device__ __forceinline__ void split1(float v, bf16& h, bf16& l) {
    h = __float2bfloat16(v);
    l = __float2bfloat16(v - __bfloat162float(h));
}
__device__ __forceinline__ void split_store4(float4 o, bf16* hi, bf16* lo) {
    bf16 h0,h1,h2,h3,l0,l1,l2,l3;
    split1(o.x,h0,l0); split1(o.y,h1,l1); split1(o.z,h2,l2); split1(o.w,h3,l3);
    *(__nv_bfloat162*)(hi)     = __halves2bfloat162(h0,h1);
    *(__nv_bfloat162*)(hi + 2) = __halves2bfloat162(h2,h3);
    *(__nv_bfloat162*)(lo)     = __halves2bfloat162(l0,l1);
    *(__nv_bfloat162*)(lo + 2) = __halves2bfloat162(l2,l3);
}

// ---------------------------------------------------------------------------
// Reductions
// ---------------------------------------------------------------------------
__device__ __forceinline__ float warpMax(float v) {
#pragma unroll
    for (int o = 16; o; o >>= 1) v = fmaxf(v, __shfl_xor_sync(0xffffffffu, v, o));
    return v;
}
__device__ __forceinline__ float warpSum(float v) {
#pragma unroll
    for (int o = 16; o; o >>= 1) v += __shfl_xor_sync(0xffffffffu, v, o);
    return v;
}

// ---------------------------------------------------------------------------
// RMSNorm -> bf16 hi/lo pair
// ---------------------------------------------------------------------------
__global__ __launch_bounds__(256) void rmsnorm_kernel(
    const float* __restrict__ x, const float* __restrict__ w,
    bf16* __restrict__ xh, bf16* __restrict__ xl)
{
    long long base = (long long)blockIdx.x * DMODEL;
    int tid = threadIdx.x;
    const float4* xr = (const float4*)(x + base);
    float4 v0 = xr[tid];
    float4 v1 = xr[tid + 256];
    float s = v0.x*v0.x + v0.y*v0.y + v0.z*v0.z + v0.w*v0.w
            + v1.x*v1.x + v1.y*v1.y + v1.z*v1.z + v1.w*v1.w;

    __shared__ float sh[8];
    s = warpSum(s);
    if ((tid & 31) == 0) sh[tid >> 5] = s;
    __syncthreads();
    float tot = 0.f;
#pragma unroll
    for (int i = 0; i < 8; i++) tot += sh[i];
    float r = rsqrtf(tot / (float)DMODEL + 1e-6f);

    const float4* wr = (const float4*)w;
    float4 w0 = wr[tid], w1 = wr[tid + 256];
    float4 o0, o1;
    o0.x = v0.x*r*w0.x; o0.y = v0.y*r*w0.y; o0.z = v0.z*r*w0.z; o0.w = v0.w*r*w0.w;
    o1.x = v1.x*r*w1.x; o1.y = v1.y*r*w1.y; o1.z = v1.z*r*w1.z; o1.w = v1.w*r*w1.w;
    split_store4(o0, xh + base + tid*4,        xl + base + tid*4);
    split_store4(o1, xh + base + 1024 + tid*4, xl + base + 1024 + tid*4);
}

// ---------------------------------------------------------------------------
// Generic fp32 -> hi/lo conversion (weights)
// ---------------------------------------------------------------------------
__global__ __launch_bounds__(256) void convert_split(
    const float* __restrict__ src, bf16* __restrict__ hi, bf16* __restrict__ lo, int n4)
{
    int i = blockIdx.x * 256 + threadIdx.x;
    if (i < n4) {
        float4 v = ((const float4*)src)[i];
        split_store4(v, hi + (long long)i*4, lo + (long long)i*4);
    }
}

// ---------------------------------------------------------------------------
// V transpose: qkv[(b*T+t), 4096 + h*128 + d] -> Vt[z=(b,h)][d][t]  (hi & lo)
// ---------------------------------------------------------------------------
__global__ __launch_bounds__(256) void vtrans_kernel(
    const bf16* __restrict__ qhi, const bf16* __restrict__ qlo,
    bf16* __restrict__ vthi, bf16* __restrict__ vtlo)
{
    __shared__ bf16 th[32][33];
    __shared__ bf16 tl[32][33];
    int z = blockIdx.z;
    int b = z >> 4, h = z & 15;
    int t0 = blockIdx.x * 32, d0 = blockIdx.y * 32;
    int tx = threadIdx.x, ty = threadIdx.y;
#pragma unroll
    for (int i = 0; i < 4; i++) {
        int t = t0 + ty + i * 8;
        int d = d0 + tx;
        long long src = (long long)(b * TSEQ + t) * QKVW + 2 * DMODEL + h * DHEAD + d;
        th[ty + i*8][tx] = qhi[src];
        tl[ty + i*8][tx] = qlo[src];
    }
    __syncthreads();
#pragma unroll
    for (int i = 0; i < 4; i++) {
        int d = d0 + ty + i * 8;
        int t = t0 + tx;
        long long dst = ((long long)z * DHEAD + d) * TSEQ + t;
        vthi[dst] = th[tx][ty + i*8];
        vtlo[dst] = tl[tx][ty + i*8];
    }
}

// ---------------------------------------------------------------------------
// Causal softmax: reads fp32 S, writes bf16 hi/lo P (full rows, zeros masked)
// ---------------------------------------------------------------------------
__global__ __launch_bounds__(256) void softmax_causal(
    const float* __restrict__ S, bf16* __restrict__ Ph, bf16* __restrict__ Pl)
{
    int i = blockIdx.x;
    long long base = (long long)blockIdx.y * TSEQ * TSEQ + (long long)i * TSEQ;
    const float* row = S + base;
    int valid = i + 1;
    int tid = threadIdx.x;

    float e[8];
    float m = -1e30f;
#pragma unroll
    for (int l = 0; l < 8; l++) {
        int j = tid + l * 256;
        float s = (j < valid) ? row[j] : -1e30f;
        e[l] = s;
        m = fmaxf(m, s);
    }

    __shared__ float sh[8];
    m = warpMax(m);
    if ((tid & 31) == 0) sh[tid >> 5] = m;
    __syncthreads();
    float bm = sh[0];
#pragma unroll
    for (int w = 1; w < 8; w++) bm = fmaxf(bm, sh[w]);
    __syncthreads();

    float sum = 0.f;
#pragma unroll
    for (int l = 0; l < 8; l++) {
        int j = tid + l * 256;
        if (j < valid) { e[l] = expf(e[l] - bm); sum += e[l]; }
        else           { e[l] = 0.f; }
    }
    sum = warpSum(sum);
    if ((tid & 31) == 0) sh[tid >> 5] = sum;
    __syncthreads();
    float bs = 0.f;
#pragma unroll
    for (int w = 0; w < 8; w++) bs += sh[w];
    float inv = 1.0f / bs;

#pragma unroll
    for (int l = 0; l < 8; l++) {
        int j = tid + l * 256;
        float v = e[l] * inv;
        bf16 h, lo;
        split1(v, h, lo);
        Ph[base + j] = h;
        Pl[base + j] = lo;
    }
}

// ---------------------------------------------------------------------------
// mma.sync primitives (sm_80-class PTX: valid on plain sm_103 target)
// ---------------------------------------------------------------------------
__device__ __forceinline__ void ldsm_x4(uint32_t& r0, uint32_t& r1, uint32_t& r2, uint32_t& r3, uint32_t addr) {
    asm volatile("ldmatrix.sync.aligned.m8n8.x4.shared.b16 {%0,%1,%2,%3}, [%4];"
        : "=r"(r0), "=r"(r1), "=r"(r2), "=r"(r3) : "r"(addr));
}
__device__ __forceinline__ void mma16816(float* d, uint32_t a0, uint32_t a1, uint32_t a2, uint32_t a3,
                                         uint32_t b0, uint32_t b1) {
    asm volatile("mma.sync.aligned.m16n8k16.row.col.f32.bf16.bf16.f32 "
        "{%0,%1,%2,%3}, {%4,%5,%6,%7}, {%8,%9}, {%0,%1,%2,%3};"
        : "+f"(d[0]), "+f"(d[1]), "+f"(d[2]), "+f"(d[3])
        : "r"(a0), "r"(a1), "r"(a2), "r"(a3), "r"(b0), "r"(b1));
}
__device__ __forceinline__ void cp16(uint32_t dst, const void* src) {
    asm volatile("cp.async.cg.shared.global [%0], [%1], 16;" :: "r"(dst), "l"(src));
}
__device__ __forceinline__ void cp_commit() {
    asm volatile("cp.async.commit_group;" ::: "memory");
}
template<int N>
__device__ __forceinline__ void cp_wait() {
    asm volatile("cp.async.wait_group %0;" :: "n"(N) : "memory");
}
__device__ __forceinline__ uint32_t smem_u32(const void* p) {
    uint32_t a;
    asm("{ .reg .u64 t; cvta.to.shared.u64 t, %1; cvt.u32.u64 %0, t; }" : "=r"(a) : "l"(p));
    return a;
}
// SW128-style swizzled address inside a [rows x 64 bf16] tile (128B rows)
__device__ __forceinline__ uint32_t sw_off(int row, int c16) {
    return (uint32_t)(row * 128 + ((c16 ^ (row & 7)) * 16));
}

// ---------------------------------------------------------------------------
// bf16x3 GEMM via mma.sync.  C[M,N] += A[M,K] * B[N,K]^T (both K-major).
// CTA tile 128x128, BK=64, 256 threads (8 warps, each 64x32).
// 3 passes: Ah*Bh, Al*Bh, Ah*Bl accumulate into the same fp32 registers.
// CAUSAL_SKIP: skip C tiles above the diagonal. KCAP: cap K at (bm+1)*128.
// EPI_BF16: write (hi,lo) bf16 pair; else fp32.
// ---------------------------------------------------------------------------
template<bool CAUSAL_SKIP, bool KCAP, bool EPI_BF16>
__global__ __launch_bounds__(256) void gemm_mma(
    const bf16* __restrict__ Ahi, const bf16* __restrict__ Alo,
    int lda, long long Ab, long long Ahs,
    const bf16* __restrict__ Bhi, const bf16* __restrict__ Blo,
    int ldb, long long Bb, long long Bhs,
    float* __restrict__ Cf, bf16* __restrict__ Chi, bf16* __restrict__ Clo,
    int ldc, long long Cb, long long Chs,
    int K, float scale)
{
    const int STAGE = 32768;          // A tile 16KB + B tile 16KB
    int bm = blockIdx.y, bn = blockIdx.x;
    if (CAUSAL_SKIP && bn > bm) return;

    extern __shared__ char smem[];
    uint32_t sbase = smem_u32(smem);

    int tid = threadIdx.x;
    int wid = tid >> 5, lane = tid & 31;
    int wm = wid >> 2, wn = wid & 3;

    long long zb = blockIdx.z >> 4, zh = blockIdx.z & 15;
    const bf16* Abase_hi = Ahi + zb*Ab + zh*Ahs + (long long)bm * 128 * lda;
    const bf16* Abase_lo = Alo + zb*Ab + zh*Ahs + (long long)bm * 128 * lda;
    const bf16* Bbase_hi = Bhi + zb*Bb + zh*Bhs + (long long)bn * 128 * ldb;
    const bf16* Bbase_lo = Blo + zb*Bb + zh*Bhs + (long long)bn * 128 * ldb;

    int Kend = K;
    if (KCAP) { int cap = (bm + 1) * 128; Kend = (cap < K) ? cap : K; }
    int itersPerPass = Kend >> 6;
    int nIter = itersPerPass * 3;

    const bf16* ApassPtr[3] = {Abase_hi, Abase_lo, Abase_hi};
    const bf16* BpassPtr[3] = {Bbase_hi, Bbase_hi, Bbase_lo};

    // per-thread load slots: 4 x 16B for A, 4 x 16B for B
    int lrow = tid >> 3;          // 0..31 (x4 rows per thread-block sweep)
    int lseg = tid & 7;           // 16B chunk within 128B row

    // load chunk (pass p, k-chunk kc) into stage buffer bufsel
    auto load_chunk = [&](int p, int kc, int bufsel) {
        const bf16* Ag = ApassPtr[p];
        const bf16* Bg = BpassPtr[p];
        int k0 = kc << 6;
        uint32_t As = sbase + bufsel * STAGE;
        uint32_t Bs = As + 16384;
#pragma unroll
        for (int i = 0; i < 4; i++) {
            int row = lrow + 32 * i;
            cp16(As + sw_off(row, lseg), Ag + (long long)row * lda + k0 + lseg * 8);
        }
#pragma unroll
        for (int i = 0; i < 4; i++) {
            int row = lrow + 32 * i;
            cp16(Bs + sw_off(row, lseg), Bg + (long long)row * ldb + k0 + lseg * 8);
        }
        cp_commit();
    };

    float acc[4][4][4];
#pragma unroll
    for (int a = 0; a < 4; a++)
#pragma unroll
        for (int b = 0; b < 4; b++)
#pragma unroll
            for (int c = 0; c < 4; c++) acc[a][b][c] = 0.f;

    // ldmatrix lane addressing (within tile)
    int lr8  = (lane & 7) + ((lane >> 3) & 1) * 8;  // row offset 0..15
    int lk16 = (lane >> 4);                          // 16B chunk (k granularity 8 bf16)

    int lp = 0, lkc = 0;   // load stream
    int cp = 0, ckc = 0;   // compute stream

    load_chunk(0, 0, 0);
    if (++lkc == itersPerPass) { lkc = 0; lp++; }

    for (int it = 0; it < nIter; ++it) {
        if (it + 1 < nIter) {
            load_chunk(lp, lkc, (it + 1) & 1);
            if (++lkc == itersPerPass) { lkc = 0; lp++; }
            cp_wait<1>();
        } else {
            cp_wait<0>();
        }
        __syncthreads();

        uint32_t As = sbase + (it & 1) * STAGE;
        uint32_t Bs = As + 16384;
#pragma unroll
        for (int ks = 0; ks < 4; ks++) {
            int c16 = ks * 2 + lk16;
            uint32_t af[4][4];
#pragma unroll
            for (int mi = 0; mi < 4; mi++) {
                int row = wm * 64 + mi * 16 + lr8;
                ldsm_x4(af[mi][0], af[mi][1], af[mi][2], af[mi][3], As + sw_off(row, c16));
            }
            uint32_t bfr[2][4];
#pragma unroll
            for (int ni = 0; ni < 2; ni++) {
                int row = wn * 32 + ni * 16 + lr8;
                ldsm_x4(bfr[ni][0], bfr[ni][1], bfr[ni][2], bfr[ni][3], Bs + sw_off(row, c16));
            }
#pragma unroll
            for (int mi = 0; mi < 4; mi++) {
#pragma unroll
                for (int ni = 0; ni < 2; ni++) {
                    mma16816(acc[mi][ni*2+0], af[mi][0], af[mi][1], af[mi][2], af[mi][3],
                             bfr[ni][0], bfr[ni][2]);
                    mma16816(acc[mi][ni*2+1], af[mi][0], af[mi][1], af[mi][2], af[mi][3],
                             bfr[ni][1], bfr[ni][3]);
                }
            }
        }
        __syncthreads();
    }

    // Epilogue: registers -> GMEM directly
    int g = lane >> 2, t = lane & 3;
    long long Cbase = zb*Cb + zh*Chs + (long long)bm * 128 * ldc + (long long)bn * 128;
#pragma unroll
    for (int mi = 0; mi < 4; mi++) {
#pragma unroll
        for (int nc = 0; nc < 4; nc++) {
            int m0 = wm * 64 + mi * 16 + g;
            int n0 = wn * 32 + nc * 8 + t * 2;
            float v0 = acc[mi][nc][0] * scale;
            float v1 = acc[mi][nc][1] * scale;
            float v2 = acc[mi][nc][2] * scale;
            float v3 = acc[mi][nc][3] * scale;
            if (EPI_BF16) {
                bf16 h0,h1,h2,h3,l0,l1,l2,l3;
                split1(v0,h0,l0); split1(v1,h1,l1); split1(v2,h2,l2); split1(v3,h3,l3);
                *(__nv_bfloat162*)(Chi + Cbase + (long long)m0*ldc + n0)       = __halves2bfloat162(h0,h1);
                *(__nv_bfloat162*)(Clo + Cbase + (long long)m0*ldc + n0)       = __halves2bfloat162(l0,l1);
                *(__nv_bfloat162*)(Chi + Cbase + (long long)(m0+8)*ldc + n0)   = __halves2bfloat162(h2,h3);
                *(__nv_bfloat162*)(Clo + Cbase + (long long)(m0+8)*ldc + n0)   = __halves2bfloat162(l2,l3);
            } else {
                *(float2*)(Cf + Cbase + (long long)m0*ldc + n0)     = make_float2(v0, v1);
                *(float2*)(Cf + Cbase + (long long)(m0+8)*ldc + n0) = make_float2(v2, v3);
            }
        }
    }
}

// ---------------------------------------------------------------------------
// Launch
// ---------------------------------------------------------------------------
extern "C" void kernel_launch(void* const* d_in, const int* in_sizes, int n_in,
                              void* d_out, int out_size)
{
    const float* x    = (const float*)d_in[0];
    const float* nw   = (const float*)d_in[1];
    const float* wqkv = (const float*)d_in[2];
    const float* wout = (const float*)d_in[3];
    float* out = (float*)d_out;

    bf16 *xnh, *xnl, *wqh, *wql, *woh, *wol, *qh, *ql, *vth, *vtl, *Ph, *Pl, *yh, *yl;
    float *S;
    cudaGetSymbolAddress((void**)&xnh, g_xn_hi);
    cudaGetSymbolAddress((void**)&xnl, g_xn_lo);
    cudaGetSymbolAddress((void**)&wqh, g_wqkv_hi);
    cudaGetSymbolAddress((void**)&wql, g_wqkv_lo);
    cudaGetSymbolAddress((void**)&woh, g_wout_hi);
    cudaGetSymbolAddress((void**)&wol, g_wout_lo);
    cudaGetSymbolAddress((void**)&qh,  g_qkv_hi);
    cudaGetSymbolAddress((void**)&ql,  g_qkv_lo);
    cudaGetSymbolAddress((void**)&vth, g_vt_hi);
    cudaGetSymbolAddress((void**)&vtl, g_vt_lo);
    cudaGetSymbolAddress((void**)&S,   g_S);
    cudaGetSymbolAddress((void**)&Ph,  g_P_hi);
    cudaGetSymbolAddress((void**)&Pl,  g_P_lo);
    cudaGetSymbolAddress((void**)&yh,  g_y_hi);
    cudaGetSymbolAddress((void**)&yl,  g_y_lo);

    const int SMEM = 2 * 32768;  // 64KB dynamic
    cudaFuncSetAttribute((const void*)gemm_mma<false,false,true >, cudaFuncAttributeMaxDynamicSharedMemorySize, SMEM);
    cudaFuncSetAttribute((const void*)gemm_mma<true, false,false>, cudaFuncAttributeMaxDynamicSharedMemorySize, SMEM);
    cudaFuncSetAttribute((const void*)gemm_mma<false,true ,true >, cudaFuncAttributeMaxDynamicSharedMemorySize, SMEM);
    cudaFuncSetAttribute((const void*)gemm_mma<false,false,false>, cudaFuncAttributeMaxDynamicSharedMemorySize, SMEM);

    // 1) RMSNorm -> xn hi/lo
    rmsnorm_kernel<<<BROWS, 256>>>(x, nw, xnh, xnl);

    // 2) weight splits
    convert_split<<<(QKVW * DMODEL / 4 + 255) / 256, 256>>>(wqkv, wqh, wql, QKVW * DMODEL / 4);
    convert_split<<<(DMODEL * DMODEL / 4 + 255) / 256, 256>>>(wout, woh, wol, DMODEL * DMODEL / 4);

    // 3) qkv = xn @ w_qkv^T  -> bf16 hi/lo pair
    gemm_mma<false,false,true><<<dim3(QKVW/128, BROWS/128, 1), 256, SMEM>>>(
        xnh, xnl, DMODEL, 0, 0,
        wqh, wql, DMODEL, 0, 0,
        nullptr, qh, ql, QKVW, 0, 0,
        DMODEL, 1.0f);

    // 4) V transpose -> Vt[z][d][t] hi/lo
    vtrans_kernel<<<dim3(TSEQ/32, DHEAD/32, NBH), dim3(32, 8)>>>(qh, ql, vth, vtl);

    const long long QKV_B = (long long)TSEQ * QKVW;
    const long long S_B   = 16LL * TSEQ * TSEQ;
    const long long S_H   = (long long)TSEQ * TSEQ;

    // 5) S = Q @ K^T / sqrt(Dh)
    gemm_mma<true,false,false><<<dim3(TSEQ/128, TSEQ/128, NBH), 256, SMEM>>>(
        qh,          ql,          QKVW, QKV_B, DHEAD,
        qh + DMODEL, ql + DMODEL, QKVW, QKV_B, DHEAD,
        S, nullptr, nullptr, TSEQ, S_B, S_H,
        DHEAD, 0.08838834764831845f);

    // 6) causal softmax -> P hi/lo
    softmax_causal<<<dim3(TSEQ, NBH), 256>>>(S, Ph, Pl);

    // 7) y = P @ V  (trapezoid K-cap) -> y hi/lo (merged heads)
    gemm_mma<false,true,true><<<dim3(1, TSEQ/128, NBH), 256, SMEM>>>(
        Ph, Pl, TSEQ, S_B, S_H,
        vth, vtl, TSEQ, (long long)16 * DHEAD * TSEQ, (long long)DHEAD * TSEQ,
        nullptr, yh, yl, DMODEL, (long long)TSEQ * DMODEL, DHEAD,
        TSEQ, 1.0f);

    // 8) out = y @ w_out^T  (fp32 to d_out)
    gemm_mma<false,false,false><<<dim3(DMODEL/128, BROWS/128, 1), 256, SMEM>>>(
        yh, yl, DMODEL, 0, 0,
        woh, wol, DMODEL, 0, 0,
        out, nullptr, nullptr, DMODEL, 0, 0,
        DMODEL, 1.0f);
}

// round 4
// speedup vs baseline: 3.0715x; 1.1168x over previous
#include <cuda_runtime.h>
#include <cuda_bf16.h>
#include <cstdint>

// Problem constants
#define TSEQ   2048
#define DMODEL 2048
#define NHEADS 16
#define DHEAD  128
#define BATCH  2
#define BROWS  (BATCH * TSEQ)      // 4096
#define QKVW   (3 * DMODEL)        // 6144
#define NBH    (BATCH * NHEADS)    // 32

typedef __nv_bfloat16 bf16;

// ---------------------------------------------------------------------------
// Scratch
// ---------------------------------------------------------------------------
__device__ bf16  g_xn_hi [(long long)BROWS * DMODEL];
__device__ bf16  g_xn_lo [(long long)BROWS * DMODEL];
__device__ bf16  g_wqkv_hi[(long long)QKVW * DMODEL];
__device__ bf16  g_wqkv_lo[(long long)QKVW * DMODEL];
__device__ bf16  g_wout_hi[(long long)DMODEL * DMODEL];
__device__ bf16  g_wout_lo[(long long)DMODEL * DMODEL];
__device__ bf16  g_qkv_hi[(long long)BROWS * QKVW];
__device__ bf16  g_qkv_lo[(long long)BROWS * QKVW];
__device__ bf16  g_y_hi  [(long long)BROWS * DMODEL];
__device__ bf16  g_y_lo  [(long long)BROWS * DMODEL];

// ---------------------------------------------------------------------------
// helpers
// ---------------------------------------------------------------------------
__device__ __forceinline__ void split1(float v, bf16& h, bf16& l) {
    h = __float2bfloat16(v);
    l = __float2bfloat16(v - __bfloat162float(h));
}
__device__ __forceinline__ uint32_t pack2(bf16 a, bf16 b) {
    __nv_bfloat162 p = __halves2bfloat162(a, b);
    return *(uint32_t*)&p;
}
__device__ __forceinline__ void split_store4(float4 o, bf16* hi, bf16* lo) {
    bf16 h0,h1,h2,h3,l0,l1,l2,l3;
    split1(o.x,h0,l0); split1(o.y,h1,l1); split1(o.z,h2,l2); split1(o.w,h3,l3);
    *(__nv_bfloat162*)(hi)     = __halves2bfloat162(h0,h1);
    *(__nv_bfloat162*)(hi + 2) = __halves2bfloat162(h2,h3);
    *(__nv_bfloat162*)(lo)     = __halves2bfloat162(l0,l1);
    *(__nv_bfloat162*)(lo + 2) = __halves2bfloat162(l2,l3);
}
__device__ __forceinline__ float warpSum(float v) {
#pragma unroll
    for (int o = 16; o; o >>= 1) v += __shfl_xor_sync(0xffffffffu, v, o);
    return v;
}

// ---------------------------------------------------------------------------
// RMSNorm -> bf16 hi/lo pair
// ---------------------------------------------------------------------------
__global__ __launch_bounds__(256) void rmsnorm_kernel(
    const float* __restrict__ x, const float* __restrict__ w,
    bf16* __restrict__ xh, bf16* __restrict__ xl)
{
    long long base = (long long)blockIdx.x * DMODEL;
    int tid = threadIdx.x;
    const float4* xr = (const float4*)(x + base);
    float4 v0 = xr[tid];
    float4 v1 = xr[tid + 256];
    float s = v0.x*v0.x + v0.y*v0.y + v0.z*v0.z + v0.w*v0.w
            + v1.x*v1.x + v1.y*v1.y + v1.z*v1.z + v1.w*v1.w;

    __shared__ float sh[8];
    s = warpSum(s);
    if ((tid & 31) == 0) sh[tid >> 5] = s;
    __syncthreads();
    float tot = 0.f;
#pragma unroll
    for (int i = 0; i < 8; i++) tot += sh[i];
    float r = rsqrtf(tot / (float)DMODEL + 1e-6f);

    const float4* wr = (const float4*)w;
    float4 w0 = wr[tid], w1 = wr[tid + 256];
    float4 o0, o1;
    o0.x = v0.x*r*w0.x; o0.y = v0.y*r*w0.y; o0.z = v0.z*r*w0.z; o0.w = v0.w*r*w0.w;
    o1.x = v1.x*r*w1.x; o1.y = v1.y*r*w1.y; o1.z = v1.z*r*w1.z; o1.w = v1.w*r*w1.w;
    split_store4(o0, xh + base + tid*4,        xl + base + tid*4);
    split_store4(o1, xh + base + 1024 + tid*4, xl + base + 1024 + tid*4);
}

// ---------------------------------------------------------------------------
// fp32 -> hi/lo conversion (weights)
// ---------------------------------------------------------------------------
__global__ __launch_bounds__(256) void convert_split(
    const float* __restrict__ src, bf16* __restrict__ hi, bf16* __restrict__ lo, int n4)
{
    int i = blockIdx.x * 256 + threadIdx.x;
    if (i < n4) {
        float4 v = ((const float4*)src)[i];
        split_store4(v, hi + (long long)i*4, lo + (long long)i*4);
    }
}

// ---------------------------------------------------------------------------
// mma.sync primitives (sm_80-class PTX: valid on plain sm_103 target)
// ---------------------------------------------------------------------------
__device__ __forceinline__ void ldsm_x4(uint32_t& r0, uint32_t& r1, uint32_t& r2, uint32_t& r3, uint32_t addr) {
    asm volatile("ldmatrix.sync.aligned.m8n8.x4.shared.b16 {%0,%1,%2,%3}, [%4];"
        : "=r"(r0), "=r"(r1), "=r"(r2), "=r"(r3) : "r"(addr));
}
__device__ __forceinline__ void ldsm_x4_t(uint32_t& r0, uint32_t& r1, uint32_t& r2, uint32_t& r3, uint32_t addr) {
    asm volatile("ldmatrix.sync.aligned.m8n8.x4.trans.shared.b16 {%0,%1,%2,%3}, [%4];"
        : "=r"(r0), "=r"(r1), "=r"(r2), "=r"(r3) : "r"(addr));
}
__device__ __forceinline__ void mma16816(float* d, uint32_t a0, uint32_t a1, uint32_t a2, uint32_t a3,
                                         uint32_t b0, uint32_t b1) {
    asm volatile("mma.sync.aligned.m16n8k16.row.col.f32.bf16.bf16.f32 "
        "{%0,%1,%2,%3}, {%4,%5,%6,%7}, {%8,%9}, {%0,%1,%2,%3};"
        : "+f"(d[0]), "+f"(d[1]), "+f"(d[2]), "+f"(d[3])
        : "r"(a0), "r"(a1), "r"(a2), "r"(a3), "r"(b0), "r"(b1));
}
__device__ __forceinline__ void cp16(uint32_t dst, const void* src) {
    asm volatile("cp.async.cg.shared.global [%0], [%1], 16;" :: "r"(dst), "l"(src));
}
__device__ __forceinline__ void cp_commit() {
    asm volatile("cp.async.commit_group;" ::: "memory");
}
template<int N>
__device__ __forceinline__ void cp_wait() {
    asm volatile("cp.async.wait_group %0;" :: "n"(N) : "memory");
}
__device__ __forceinline__ uint32_t smem_u32(const void* p) {
    uint32_t a;
    asm("{ .reg .u64 t; cvta.to.shared.u64 t, %1; cvt.u32.u64 %0, t; }" : "=r"(a) : "l"(p));
    return a;
}
// swizzled addr inside a [rows x 128 bf16] tile (256B rows, 16 x 16B chunks)
__device__ __forceinline__ uint32_t swz256(int row, int ch) {
    return (uint32_t)(row * 256 + ((ch ^ (row & 7)) * 16));
}
// swizzled addr inside a [rows x 64 bf16] tile (128B rows) -- dense GEMM
__device__ __forceinline__ uint32_t sw_off(int row, int c16) {
    return (uint32_t)(row * 128 + ((c16 ^ (row & 7)) * 16));
}

// ---------------------------------------------------------------------------
// bf16x3 dense GEMM via mma.sync (unchanged from R2 core).
// ---------------------------------------------------------------------------
template<bool EPI_BF16>
__global__ __launch_bounds__(256) void gemm_mma(
    const bf16* __restrict__ Ahi, const bf16* __restrict__ Alo, int lda,
    const bf16* __restrict__ Bhi, const bf16* __restrict__ Blo, int ldb,
    float* __restrict__ Cf, bf16* __restrict__ Chi, bf16* __restrict__ Clo, int ldc,
    int K)
{
    const int STAGE = 32768;
    int bm = blockIdx.y, bn = blockIdx.x;

    extern __shared__ char smem[];
    uint32_t sbase = smem_u32(smem);

    int tid = threadIdx.x;
    int wid = tid >> 5, lane = tid & 31;
    int wm = wid >> 2, wn = wid & 3;

    const bf16* Abase_hi = Ahi + (long long)bm * 128 * lda;
    const bf16* Abase_lo = Alo + (long long)bm * 128 * lda;
    const bf16* Bbase_hi = Bhi + (long long)bn * 128 * ldb;
    const bf16* Bbase_lo = Blo + (long long)bn * 128 * ldb;

    int itersPerPass = K >> 6;
    int nIter = itersPerPass * 3;

    const bf16* ApassPtr[3] = {Abase_hi, Abase_lo, Abase_hi};
    const bf16* BpassPtr[3] = {Bbase_hi, Bbase_hi, Bbase_lo};

    int lrow = tid >> 3;
    int lseg = tid & 7;

    auto load_chunk = [&](int p, int kc, int bufsel) {
        const bf16* Ag = ApassPtr[p];
        const bf16* Bg = BpassPtr[p];
        int k0 = kc << 6;
        uint32_t As = sbase + bufsel * STAGE;
        uint32_t Bs = As + 16384;
#pragma unroll
        for (int i = 0; i < 4; i++) {
            int row = lrow + 32 * i;
            cp16(As + sw_off(row, lseg), Ag + (long long)row * lda + k0 + lseg * 8);
        }
#pragma unroll
        for (int i = 0; i < 4; i++) {
            int row = lrow + 32 * i;
            cp16(Bs + sw_off(row, lseg), Bg + (long long)row * ldb + k0 + lseg * 8);
        }
        cp_commit();
    };

    float acc[4][4][4];
#pragma unroll
    for (int a = 0; a < 4; a++)
#pragma unroll
        for (int b = 0; b < 4; b++)
#pragma unroll
            for (int c = 0; c < 4; c++) acc[a][b][c] = 0.f;

    int lr8  = (lane & 7) + ((lane >> 3) & 1) * 8;
    int lk16 = (lane >> 4);

    int lp = 0, lkc = 0;

    load_chunk(0, 0, 0);
    if (++lkc == itersPerPass) { lkc = 0; lp++; }

    for (int it = 0; it < nIter; ++it) {
        if (it + 1 < nIter) {
            load_chunk(lp, lkc, (it + 1) & 1);
            if (++lkc == itersPerPass) { lkc = 0; lp++; }
            cp_wait<1>();
        } else {
            cp_wait<0>();
        }
        __syncthreads();

        uint32_t As = sbase + (it & 1) * STAGE;
        uint32_t Bs = As + 16384;
#pragma unroll
        for (int ks = 0; ks < 4; ks++) {
            int c16 = ks * 2 + lk16;
            uint32_t af[4][4];
#pragma unroll
            for (int mi = 0; mi < 4; mi++) {
                int row = wm * 64 + mi * 16 + lr8;
                ldsm_x4(af[mi][0], af[mi][1], af[mi][2], af[mi][3], As + sw_off(row, c16));
            }
            uint32_t bfr[2][4];
#pragma unroll
            for (int ni = 0; ni < 2; ni++) {
                int row = wn * 32 + ni * 16 + lr8;
                ldsm_x4(bfr[ni][0], bfr[ni][1], bfr[ni][2], bfr[ni][3], Bs + sw_off(row, c16));
            }
#pragma unroll
            for (int mi = 0; mi < 4; mi++) {
#pragma unroll
                for (int ni = 0; ni < 2; ni++) {
                    mma16816(acc[mi][ni*2+0], af[mi][0], af[mi][1], af[mi][2], af[mi][3],
                             bfr[ni][0], bfr[ni][2]);
                    mma16816(acc[mi][ni*2+1], af[mi][0], af[mi][1], af[mi][2], af[mi][3],
                             bfr[ni][1], bfr[ni][3]);
                }
            }
        }
        __syncthreads();
    }

    int g = lane >> 2, t = lane & 3;
    long long Cbase = (long long)bm * 128 * ldc + (long long)bn * 128;
#pragma unroll
    for (int mi = 0; mi < 4; mi++) {
#pragma unroll
        for (int nc = 0; nc < 4; nc++) {
            int m0 = wm * 64 + mi * 16 + g;
            int n0 = wn * 32 + nc * 8 + t * 2;
            float v0 = acc[mi][nc][0];
            float v1 = acc[mi][nc][1];
            float v2 = acc[mi][nc][2];
            float v3 = acc[mi][nc][3];
            if (EPI_BF16) {
                bf16 h0,h1,h2,h3,l0,l1,l2,l3;
                split1(v0,h0,l0); split1(v1,h1,l1); split1(v2,h2,l2); split1(v3,h3,l3);
                *(__nv_bfloat162*)(Chi + Cbase + (long long)m0*ldc + n0)       = __halves2bfloat162(h0,h1);
                *(__nv_bfloat162*)(Clo + Cbase + (long long)m0*ldc + n0)       = __halves2bfloat162(l0,l1);
                *(__nv_bfloat162*)(Chi + Cbase + (long long)(m0+8)*ldc + n0)   = __halves2bfloat162(h2,h3);
                *(__nv_bfloat162*)(Clo + Cbase + (long long)(m0+8)*ldc + n0)   = __halves2bfloat162(l2,l3);
            } else {
                *(float2*)(Cf + Cbase + (long long)m0*ldc + n0)     = make_float2(v0, v1);
                *(float2*)(Cf + Cbase + (long long)(m0+8)*ldc + n0) = make_float2(v2, v3);
            }
        }
    }
}

// ---------------------------------------------------------------------------
// Fused flash attention (causal), bf16x3 both GEMMs.
// Grid (16, 32): qb = 15 - blockIdx.x (heavy first), z = (b,h).
// 8 warps, each owns 16 q rows x 128 keys. smem: Q,K,V hi/lo = 192KB.
// ---------------------------------------------------------------------------
__global__ __launch_bounds__(256, 1) void flash_attn(
    const bf16* __restrict__ qkvh, const bf16* __restrict__ qkvl,
    bf16* __restrict__ yh, bf16* __restrict__ yl)
{
    extern __shared__ char smem[];
    uint32_t sb = smem_u32(smem);
    const uint32_t Qhs = sb,            Qls = sb + 32768;
    const uint32_t Khs = sb + 65536,    Kls = sb + 98304;
    const uint32_t Vhs = sb + 131072,   Vls = sb + 163840;

    int tid = threadIdx.x, lane = tid & 31, wid = tid >> 5;
    int qb = (int)(gridDim.x - 1) - (int)blockIdx.x;
    int z = blockIdx.y; int b = z >> 4, h = z & 15;
    long long rowQ0 = (long long)b * TSEQ + (long long)qb * 128;
    long long rowKV = (long long)b * TSEQ;
    int colQ = h * DHEAD, colK = DMODEL + h * DHEAD, colV = 2*DMODEL + h * DHEAD;

    auto load_tile = [&](uint32_t dst, const bf16* gp, long long grow0, int col0) {
#pragma unroll
        for (int i = 0; i < 8; i++) {
            int lin = tid + 256 * i;
            int row = lin >> 4, ch = lin & 15;
            cp16(dst + swz256(row, ch), gp + (grow0 + row) * QKVW + col0 + ch * 8);
        }
    };

    // prologue: G0 = Q + K(0); G1 = V(0)
    load_tile(Qhs, qkvh, rowQ0, colQ);
    load_tile(Qls, qkvl, rowQ0, colQ);
    load_tile(Khs, qkvh, rowKV, colK);
    load_tile(Kls, qkvl, rowKV, colK);
    cp_commit();
    load_tile(Vhs, qkvh, rowKV, colV);
    load_tile(Vls, qkvl, rowKV, colV);
    cp_commit();

    float sacc[16][4];
    float oacc[16][4];
#pragma unroll
    for (int i=0;i<16;i++) { oacc[i][0]=0.f; oacc[i][1]=0.f; oacc[i][2]=0.f; oacc[i][3]=0.f; }
    float m0 = -1e30f, m1 = -1e30f, l0 = 0.f, l1 = 0.f;

    int g = lane >> 2, t = lane & 3;
    int wr = wid * 16;
    int lr8  = (lane & 7) + ((lane >> 3) & 1) * 8;   // A/B ldsm row bits
    int lk16 = lane >> 4;
    int vr8  = (lane & 7) + ((lane >> 4) & 1) * 8;   // trans-B ldsm row bits
    int vc   = (lane >> 3) & 1;

    const float sm_scale = 0.08838834764831845f;
    int q0row = qb * 128 + wr + g;
    int q1row = q0row + 8;

    for (int j = 0; j <= qb; ++j) {
        cp_wait<1>();
        __syncthreads();           // K(j) (and Q) visible

        // ---- S = Qh*Kh + Ql*Kh  then + Qh*Kl ----
#pragma unroll
        for (int i=0;i<16;i++) { sacc[i][0]=0.f; sacc[i][1]=0.f; sacc[i][2]=0.f; sacc[i][3]=0.f; }
#pragma unroll
        for (int c = 0; c < 8; c++) {
            int ch = 2*c + lk16;
            int arow = wr + lr8;
            uint32_t ah0,ah1,ah2,ah3, al0,al1,al2,al3;
            ldsm_x4(ah0,ah1,ah2,ah3, Qhs + swz256(arow, ch));
            ldsm_x4(al0,al1,al2,al3, Qls + swz256(arow, ch));
#pragma unroll
            for (int nn = 0; nn < 8; nn++) {
                uint32_t r0,r1,r2,r3;
                ldsm_x4(r0,r1,r2,r3, Khs + swz256(nn*16 + lr8, ch));
                mma16816(sacc[2*nn],   ah0,ah1,ah2,ah3, r0, r2);
                mma16816(sacc[2*nn+1], ah0,ah1,ah2,ah3, r1, r3);
                mma16816(sacc[2*nn],   al0,al1,al2,al3, r0, r2);
                mma16816(sacc[2*nn+1], al0,al1,al2,al3, r1, r3);
            }
        }
#pragma unroll
        for (int c = 0; c < 8; c++) {
            int ch = 2*c + lk16;
            int arow = wr + lr8;
            uint32_t ah0,ah1,ah2,ah3;
            ldsm_x4(ah0,ah1,ah2,ah3, Qhs + swz256(arow, ch));
#pragma unroll
            for (int nn = 0; nn < 8; nn++) {
                uint32_t r0,r1,r2,r3;
                ldsm_x4(r0,r1,r2,r3, Kls + swz256(nn*16 + lr8, ch));
                mma16816(sacc[2*nn],   ah0,ah1,ah2,ah3, r0, r2);
                mma16816(sacc[2*nn+1], ah0,ah1,ah2,ah3, r1, r3);
            }
        }

        // ---- online softmax ----
        float nm0 = -1e30f, nm1 = -1e30f;
        bool diag = (j == qb);
#pragma unroll
        for (int i = 0; i < 16; i++) {
            int kc = j*128 + i*8 + 2*t;
            float s0 = sacc[i][0]*sm_scale, s1 = sacc[i][1]*sm_scale;
            float s2 = sacc[i][2]*sm_scale, s3 = sacc[i][3]*sm_scale;
            if (diag) {
                if (kc     > q0row) s0 = -1e30f;
                if (kc + 1 > q0row) s1 = -1e30f;
                if (kc     > q1row) s2 = -1e30f;
                if (kc + 1 > q1row) s3 = -1e30f;
            }
            sacc[i][0]=s0; sacc[i][1]=s1; sacc[i][2]=s2; sacc[i][3]=s3;
            nm0 = fmaxf(nm0, fmaxf(s0, s1));
            nm1 = fmaxf(nm1, fmaxf(s2, s3));
        }
        nm0 = fmaxf(nm0, __shfl_xor_sync(0xffffffffu, nm0, 1));
        nm0 = fmaxf(nm0, __shfl_xor_sync(0xffffffffu, nm0, 2));
        nm1 = fmaxf(nm1, __shfl_xor_sync(0xffffffffu, nm1, 1));
        nm1 = fmaxf(nm1, __shfl_xor_sync(0xffffffffu, nm1, 2));
        nm0 = fmaxf(m0, nm0); nm1 = fmaxf(m1, nm1);
        float al0 = __expf(m0 - nm0), al1 = __expf(m1 - nm1);
        m0 = nm0; m1 = nm1;

        float rs0 = 0.f, rs1 = 0.f;
#pragma unroll
        for (int i = 0; i < 16; i++) {
            float e0 = __expf(sacc[i][0] - nm0);
            float e1 = __expf(sacc[i][1] - nm0);
            float e2 = __expf(sacc[i][2] - nm1);
            float e3 = __expf(sacc[i][3] - nm1);
            rs0 += e0 + e1; rs1 += e2 + e3;
            sacc[i][0]=e0; sacc[i][1]=e1; sacc[i][2]=e2; sacc[i][3]=e3;
        }
        rs0 += __shfl_xor_sync(0xffffffffu, rs0, 1);
        rs0 += __shfl_xor_sync(0xffffffffu, rs0, 2);
        rs1 += __shfl_xor_sync(0xffffffffu, rs1, 1);
        rs1 += __shfl_xor_sync(0xffffffffu, rs1, 2);
        l0 = l0*al0 + rs0; l1 = l1*al1 + rs1;
#pragma unroll
        for (int i = 0; i < 16; i++) {
            oacc[i][0]*=al0; oacc[i][1]*=al0; oacc[i][2]*=al1; oacc[i][3]*=al1;
        }

        __syncthreads();           // all warps done reading K
        if (j < qb) {
            load_tile(Khs, qkvh, rowKV + (long long)(j+1)*128, colK);
            load_tile(Kls, qkvl, rowKV + (long long)(j+1)*128, colK);
        }
        cp_commit();               // G: K(j+1) (possibly empty)

        // ---- pack P hi/lo ----
        uint32_t ph[16][2], pl[16][2];
#pragma unroll
        for (int i = 0; i < 16; i++) {
            bf16 h0,h1,h2,h3, q0,q1,q2,q3;
            split1(sacc[i][0],h0,q0); split1(sacc[i][1],h1,q1);
            split1(sacc[i][2],h2,q2); split1(sacc[i][3],h3,q3);
            ph[i][0] = pack2(h0,h1); ph[i][1] = pack2(h2,h3);
            pl[i][0] = pack2(q0,q1); pl[i][1] = pack2(q2,q3);
        }

        cp_wait<1>();
        __syncthreads();           // V(j) visible

        // ---- O += P * V  (Ph*Vh + Pl*Vh + Ph*Vl) ----
#pragma unroll
        for (int kk = 0; kk < 8; kk++) {
            uint32_t pa0 = ph[2*kk][0], pa1 = ph[2*kk][1], pa2 = ph[2*kk+1][0], pa3 = ph[2*kk+1][1];
            uint32_t qa0 = pl[2*kk][0], qa1 = pl[2*kk][1], qa2 = pl[2*kk+1][0], qa3 = pl[2*kk+1][1];
            int vrow = kk*16 + vr8;
#pragma unroll
            for (int nn = 0; nn < 8; nn++) {
                int ch = nn*2 + vc;
                uint32_t r0,r1,r2,r3;
                ldsm_x4_t(r0,r1,r2,r3, Vhs + swz256(vrow, ch));
                mma16816(oacc[2*nn],   pa0,pa1,pa2,pa3, r0, r2);
                mma16816(oacc[2*nn+1], pa0,pa1,pa2,pa3, r1, r3);
                mma16816(oacc[2*nn],   qa0,qa1,qa2,qa3, r0, r2);
                mma16816(oacc[2*nn+1], qa0,qa1,qa2,qa3, r1, r3);
                ldsm_x4_t(r0,r1,r2,r3, Vls + swz256(vrow, ch));
                mma16816(oacc[2*nn],   pa0,pa1,pa2,pa3, r0, r2);
                mma16816(oacc[2*nn+1], pa0,pa1,pa2,pa3, r1, r3);
            }
        }

        __syncthreads();           // all warps done reading V
        if (j < qb) {
            load_tile(Vhs, qkvh, rowKV + (long long)(j+1)*128, colV);
            load_tile(Vls, qkvl, rowKV + (long long)(j+1)*128, colV);
        }
        cp_commit();               // G: V(j+1) (possibly empty)
    }

    // ---- finalize + write y hi/lo ----
    float i0 = 1.0f / l0, i1 = 1.0f / l1;
    long long r0w = (rowQ0 + wr + g) * DMODEL;
    long long r1w = r0w + 8LL * DMODEL;
#pragma unroll
    for (int i = 0; i < 16; i++) {
        int col = h * DHEAD + i*8 + 2*t;
        float v0 = oacc[i][0]*i0, v1 = oacc[i][1]*i0;
        float v2 = oacc[i][2]*i1, v3 = oacc[i][3]*i1;
        bf16 h0,h1,h2,h3, q0,q1,q2,q3;
        split1(v0,h0,q0); split1(v1,h1,q1); split1(v2,h2,q2); split1(v3,h3,q3);
        *(__nv_bfloat162*)(yh + r0w + col) = __halves2bfloat162(h0,h1);
        *(__nv_bfloat162*)(yl + r0w + col) = __halves2bfloat162(q0,q1);
        *(__nv_bfloat162*)(yh + r1w + col) = __halves2bfloat162(h2,h3);
        *(__nv_bfloat162*)(yl + r1w + col) = __halves2bfloat162(q2,q3);
    }
}

// ---------------------------------------------------------------------------
// Launch
// ---------------------------------------------------------------------------
extern "C" void kernel_launch(void* const* d_in, const int* in_sizes, int n_in,
                              void* d_out, int out_size)
{
    const float* x    = (const float*)d_in[0];
    const float* nw   = (const float*)d_in[1];
    const float* wqkv = (const float*)d_in[2];
    const float* wout = (const float*)d_in[3];
    float* out = (float*)d_out;

    bf16 *xnh, *xnl, *wqh, *wql, *woh, *wol, *qh, *ql, *yh, *yl;
    cudaGetSymbolAddress((void**)&xnh, g_xn_hi);
    cudaGetSymbolAddress((void**)&xnl, g_xn_lo);
    cudaGetSymbolAddress((void**)&wqh, g_wqkv_hi);
    cudaGetSymbolAddress((void**)&wql, g_wqkv_lo);
    cudaGetSymbolAddress((void**)&woh, g_wout_hi);
    cudaGetSymbolAddress((void**)&wol, g_wout_lo);
    cudaGetSymbolAddress((void**)&qh,  g_qkv_hi);
    cudaGetSymbolAddress((void**)&ql,  g_qkv_lo);
    cudaGetSymbolAddress((void**)&yh,  g_y_hi);
    cudaGetSymbolAddress((void**)&yl,  g_y_lo);

    const int SMEM = 2 * 32768;
    const int FSMEM = 6 * 32768;   // 192KB
    cudaFuncSetAttribute((const void*)gemm_mma<true >, cudaFuncAttributeMaxDynamicSharedMemorySize, SMEM);
    cudaFuncSetAttribute((const void*)gemm_mma<false>, cudaFuncAttributeMaxDynamicSharedMemorySize, SMEM);
    cudaFuncSetAttribute((const void*)flash_attn, cudaFuncAttributeMaxDynamicSharedMemorySize, FSMEM);

    // 1) RMSNorm -> xn hi/lo
    rmsnorm_kernel<<<BROWS, 256>>>(x, nw, xnh, xnl);

    // 2) weight splits
    convert_split<<<(QKVW * DMODEL / 4 + 255) / 256, 256>>>(wqkv, wqh, wql, QKVW * DMODEL / 4);
    convert_split<<<(DMODEL * DMODEL / 4 + 255) / 256, 256>>>(wout, woh, wol, DMODEL * DMODEL / 4);

    // 3) qkv = xn @ w_qkv^T  -> bf16 hi/lo pair
    gemm_mma<true><<<dim3(QKVW/128, BROWS/128), 256, SMEM>>>(
        xnh, xnl, DMODEL,
        wqh, wql, DMODEL,
        nullptr, qh, ql, QKVW,
        DMODEL);

    // 4) fused flash attention -> y hi/lo (merged heads)
    flash_attn<<<dim3(TSEQ/128, NBH), 256, FSMEM>>>(qh, ql, yh, yl);

    // 5) out = y @ w_out^T  (fp32 to d_out)
    gemm_mma<false><<<dim3(DMODEL/128, BROWS/128), 256, SMEM>>>(
        yh, yl, DMODEL,
        woh, wol, DMODEL,
        out, nullptr, nullptr, DMODEL,
        DMODEL);
}